// round 4
// baseline (speedup 1.0000x reference)
#include <cuda_runtime.h>
#include <cuda_bf16.h>
#include <math.h>

// Problem constants
#define TT   4096      // tokens = B*S
#define DD   1024      // model dim
#define HH   1024      // hidden dim
#define EE   16        // experts
#define KK   2         // top-k
#define CAP  640       // capacity = ceil(T*K/E*1.25)
#define CBUF 1280      // K*capacity

// GEMM tiling
#define BM 128
#define BN 64
#define BKD 16

// ---------------- device scratch (no allocations allowed) ----------------
__device__ int   g_topk_idx[TT * KK];
__device__ float g_topk_w[TT * KK];
__device__ int   g_disp_tok[EE * CBUF];
__device__ float g_disp_w[EE * CBUF];
__device__ int   g_count[EE];
__device__ float g_hidden[(size_t)EE * CBUF * HH];   // ~84 MB scratch

// ---------------- kernel 0: zero output ----------------
__global__ void zero_out_kernel(float* __restrict__ out) {
    out[(size_t)blockIdx.x * 1024 + threadIdx.x] = 0.0f;
}

// ---------------- kernel 1: router (GEMV + softmax + top2) ----------------
// one warp per token
__global__ void router_kernel(const float* __restrict__ x,
                              const float* __restrict__ rw) {
    int warp = (blockIdx.x * blockDim.x + threadIdx.x) >> 5;
    int lane = threadIdx.x & 31;
    if (warp >= TT) return;
    const float* xr = x + (size_t)warp * DD;

    float acc[EE];
#pragma unroll
    for (int e = 0; e < EE; e++) acc[e] = 0.0f;

    for (int d = lane; d < DD; d += 32) {
        float xv = __ldg(xr + d);
        const float4* rwp = (const float4*)(rw + (size_t)d * EE);
#pragma unroll
        for (int q = 0; q < 4; q++) {
            float4 v = __ldg(rwp + q);
            acc[4 * q + 0] += xv * v.x;
            acc[4 * q + 1] += xv * v.y;
            acc[4 * q + 2] += xv * v.z;
            acc[4 * q + 3] += xv * v.w;
        }
    }
#pragma unroll
    for (int e = 0; e < EE; e++) {
#pragma unroll
        for (int off = 16; off; off >>= 1)
            acc[e] += __shfl_xor_sync(0xffffffffu, acc[e], off);
    }

    if (lane == 0) {
        // top-2 on logits (softmax is monotonic); ascending scan + strict '>'
        // matches lax.top_k tie-break (lowest index wins).
        int i1 = 0; float v1 = acc[0];
#pragma unroll
        for (int e = 1; e < EE; e++) if (acc[e] > v1) { v1 = acc[e]; i1 = e; }
        int i2 = -1; float v2 = -1e30f;
#pragma unroll
        for (int e = 0; e < EE; e++) {
            if (e == i1) continue;
            if (acc[e] > v2) { v2 = acc[e]; i2 = e; }
        }
        // softmax probs for the two winners
        float mx = v1;               // v1 is the max logit
        float s = 0.0f;
#pragma unroll
        for (int e = 0; e < EE; e++) s += expf(acc[e] - mx);
        float w1 = expf(v1 - mx) / s;
        float w2 = expf(v2 - mx) / s;
        g_topk_idx[warp * 2 + 0] = i1;
        g_topk_idx[warp * 2 + 1] = i2;
        g_topk_w[warp * 2 + 0] = w1;
        g_topk_w[warp * 2 + 1] = w2;
    }
}

// ---------------- kernel 2: ordered rank scan + compaction ----------------
// single block, 512 threads. Threads [0,256) handle k=0, [256,512) handle k=1.
// Each thread owns 16 consecutive tokens. keep = (rank within (k,e), token
// order) < CAP. Slot order within an expert is irrelevant to the final
// output, so compaction uses shared atomics.
__global__ void scan_kernel() {
    __shared__ int cnt[512][EE];     // 32 KB
    __shared__ int ecount[EE];
    int tid = threadIdx.x;
    int k = tid >> 8;
    int c = tid & 255;
    int t0 = c * 16;

#pragma unroll
    for (int e = 0; e < EE; e++) cnt[tid][e] = 0;
    if (tid < EE) ecount[tid] = 0;
    __syncthreads();

    // phase 1: per-chunk histograms
    for (int i = 0; i < 16; i++) {
        int e = g_topk_idx[(t0 + i) * 2 + k];
        cnt[tid][e]++;
    }
    __syncthreads();

    // phase 2: exclusive prefix across the 256 chunks, per (k,e)
    if (tid < 32) {
        int kk = tid >> 4, ee = tid & 15;
        int run = 0;
        for (int cc = 0; cc < 256; cc++) {
            int idx = kk * 256 + cc;
            int v = cnt[idx][ee];
            cnt[idx][ee] = run;
            run += v;
        }
    }
    __syncthreads();

    // phase 3: replay, decide keep, compact
    for (int i = 0; i < 16; i++) {
        int t = t0 + i;
        int e = g_topk_idx[t * 2 + k];
        float w = g_topk_w[t * 2 + k];
        int rank = cnt[tid][e]++;
        if (rank < CAP) {
            int slot = atomicAdd(&ecount[e], 1);
            g_disp_tok[e * CBUF + slot] = t;
            g_disp_w[e * CBUF + slot] = w;
        }
    }
    __syncthreads();
    if (tid < EE) g_count[tid] = ecount[tid];
}

// ---------------- kernel 3: fused gate/up GEMM + silu ----------------
// C[e][row][h] = silu(x_tok . gate_w[e,:,h]) * (x_tok . up_w[e,:,h])
// grid: (HH/BN, CBUF/BM, EE), 256 threads, thread tile 8x4 (x2 matrices)
__global__ __launch_bounds__(256, 2)
void gemm1_kernel(const float* __restrict__ x,
                  const float* __restrict__ gw,
                  const float* __restrict__ uw) {
    int e  = blockIdx.z;
    int m  = g_count[e];
    int m0 = blockIdx.y * BM;
    if (m0 >= m) return;
    int h0 = blockIdx.x * BN;

    __shared__ float As[BKD][BM];
    __shared__ float Bg[BKD][BN];
    __shared__ float Bu[BKD][BN];

    int tid = threadIdx.x;
    int tx = tid & 15;       // 16 col groups * 4 cols
    int ty = tid >> 4;       // 16 row groups * 8 rows

    // A-load mapping: 2 float4 per thread
    int rowA0 = tid >> 2;            // 0..63
    int rowA1 = rowA0 + 64;
    int c4 = (tid & 3) * 4;
    int tokA0 = (m0 + rowA0 < m) ? g_disp_tok[e * CBUF + m0 + rowA0] : 0;
    int tokA1 = (m0 + rowA1 < m) ? g_disp_tok[e * CBUF + m0 + rowA1] : 0;
    const float* xA0 = x + (size_t)tokA0 * DD + c4;
    const float* xA1 = x + (size_t)tokA1 * DD + c4;

    // B-load mapping: 1 float4 per thread per matrix
    int kb = tid >> 4;               // 0..15
    int hq = (tid & 15) * 4;
    const float* gwe = gw + (size_t)e * DD * HH + (size_t)kb * HH + h0 + hq;
    const float* uwe = uw + (size_t)e * DD * HH + (size_t)kb * HH + h0 + hq;

    float accg[8][4], accu[8][4];
#pragma unroll
    for (int i = 0; i < 8; i++)
#pragma unroll
        for (int j = 0; j < 4; j++) { accg[i][j] = 0.0f; accu[i][j] = 0.0f; }

    for (int k0 = 0; k0 < DD; k0 += BKD) {
        float4 a0 = *(const float4*)(xA0 + k0);
        float4 a1 = *(const float4*)(xA1 + k0);
        float4 bg = *(const float4*)(gwe + (size_t)k0 * HH);
        float4 bu = *(const float4*)(uwe + (size_t)k0 * HH);
        __syncthreads();
        As[c4 + 0][rowA0] = a0.x; As[c4 + 1][rowA0] = a0.y;
        As[c4 + 2][rowA0] = a0.z; As[c4 + 3][rowA0] = a0.w;
        As[c4 + 0][rowA1] = a1.x; As[c4 + 1][rowA1] = a1.y;
        As[c4 + 2][rowA1] = a1.z; As[c4 + 3][rowA1] = a1.w;
        *(float4*)&Bg[kb][hq] = bg;
        *(float4*)&Bu[kb][hq] = bu;
        __syncthreads();
#pragma unroll
        for (int kk = 0; kk < BKD; kk++) {
            float4 av0 = *(float4*)&As[kk][ty * 8];
            float4 av1 = *(float4*)&As[kk][ty * 8 + 4];
            float4 bgv = *(float4*)&Bg[kk][tx * 4];
            float4 buv = *(float4*)&Bu[kk][tx * 4];
            float a[8] = {av0.x, av0.y, av0.z, av0.w, av1.x, av1.y, av1.z, av1.w};
            float bgj[4] = {bgv.x, bgv.y, bgv.z, bgv.w};
            float buj[4] = {buv.x, buv.y, buv.z, buv.w};
#pragma unroll
            for (int i = 0; i < 8; i++)
#pragma unroll
                for (int j = 0; j < 4; j++) {
                    accg[i][j] += a[i] * bgj[j];
                    accu[i][j] += a[i] * buj[j];
                }
        }
    }

    // epilogue: hidden = silu(gate) * up
#pragma unroll
    for (int i = 0; i < 8; i++) {
        int gr = m0 + ty * 8 + i;
        if (gr < m) {
            float4 hv;
            float g0 = accg[i][0], g1 = accg[i][1], g2 = accg[i][2], g3 = accg[i][3];
            hv.x = (g0 / (1.0f + expf(-g0))) * accu[i][0];
            hv.y = (g1 / (1.0f + expf(-g1))) * accu[i][1];
            hv.z = (g2 / (1.0f + expf(-g2))) * accu[i][2];
            hv.w = (g3 / (1.0f + expf(-g3))) * accu[i][3];
            *(float4*)&g_hidden[((size_t)e * CBUF + gr) * HH + h0 + tx * 4] = hv;
        }
    }
}

// ---------------- kernel 4: down GEMM + weighted scatter-add ----------------
__global__ __launch_bounds__(256, 2)
void gemm2_kernel(const float* __restrict__ dw, float* __restrict__ out) {
    int e  = blockIdx.z;
    int m  = g_count[e];
    int m0 = blockIdx.y * BM;
    if (m0 >= m) return;
    int d0 = blockIdx.x * BN;

    __shared__ float As[BKD][BM];
    __shared__ float Bs[BKD][BN];

    int tid = threadIdx.x;
    int tx = tid & 15;
    int ty = tid >> 4;

    int rowA0 = tid >> 2;
    int rowA1 = rowA0 + 64;
    int c4 = (tid & 3) * 4;
    const float* hA0 = g_hidden + ((size_t)e * CBUF + m0 + rowA0) * HH + c4;
    const float* hA1 = g_hidden + ((size_t)e * CBUF + m0 + rowA1) * HH + c4;

    int kb = tid >> 4;
    int hq = (tid & 15) * 4;
    const float* dwe = dw + (size_t)e * HH * DD + (size_t)kb * DD + d0 + hq;

    float acc[8][4];
#pragma unroll
    for (int i = 0; i < 8; i++)
#pragma unroll
        for (int j = 0; j < 4; j++) acc[i][j] = 0.0f;

    for (int k0 = 0; k0 < HH; k0 += BKD) {
        float4 a0 = *(const float4*)(hA0 + k0);
        float4 a1 = *(const float4*)(hA1 + k0);
        float4 b  = *(const float4*)(dwe + (size_t)k0 * DD);
        __syncthreads();
        As[c4 + 0][rowA0] = a0.x; As[c4 + 1][rowA0] = a0.y;
        As[c4 + 2][rowA0] = a0.z; As[c4 + 3][rowA0] = a0.w;
        As[c4 + 0][rowA1] = a1.x; As[c4 + 1][rowA1] = a1.y;
        As[c4 + 2][rowA1] = a1.z; As[c4 + 3][rowA1] = a1.w;
        *(float4*)&Bs[kb][hq] = b;
        __syncthreads();
#pragma unroll
        for (int kk = 0; kk < BKD; kk++) {
            float4 av0 = *(float4*)&As[kk][ty * 8];
            float4 av1 = *(float4*)&As[kk][ty * 8 + 4];
            float4 bv  = *(float4*)&Bs[kk][tx * 4];
            float a[8] = {av0.x, av0.y, av0.z, av0.w, av1.x, av1.y, av1.z, av1.w};
            float bj[4] = {bv.x, bv.y, bv.z, bv.w};
#pragma unroll
            for (int i = 0; i < 8; i++)
#pragma unroll
                for (int j = 0; j < 4; j++) acc[i][j] += a[i] * bj[j];
        }
    }

    // epilogue: scale by gate weight, scatter-add to token row
#pragma unroll
    for (int i = 0; i < 8; i++) {
        int gr = m0 + ty * 8 + i;
        if (gr < m) {
            int tok = g_disp_tok[e * CBUF + gr];
            float w = g_disp_w[e * CBUF + gr];
            float* op = out + (size_t)tok * DD + d0 + tx * 4;
            atomicAdd(op + 0, acc[i][0] * w);
            atomicAdd(op + 1, acc[i][1] * w);
            atomicAdd(op + 2, acc[i][2] * w);
            atomicAdd(op + 3, acc[i][3] * w);
        }
    }
}

// ---------------- launcher ----------------
extern "C" void kernel_launch(void* const* d_in, const int* in_sizes, int n_in,
                              void* d_out, int out_size) {
    const float* x  = (const float*)d_in[0];
    const float* rw = (const float*)d_in[1];
    const float* gw = (const float*)d_in[2];
    const float* uw = (const float*)d_in[3];
    const float* dw = (const float*)d_in[4];
    float* out = (float*)d_out;

    zero_out_kernel<<<TT, 1024>>>(out);
    router_kernel<<<TT / 8, 256>>>(x, rw);
    scan_kernel<<<1, 512>>>();
    gemm1_kernel<<<dim3(HH / BN, CBUF / BM, EE), 256>>>(x, gw, uw);
    gemm2_kernel<<<dim3(DD / BN, CBUF / BM, EE), 256>>>(dw, out);
}

// round 5
// speedup vs baseline: 1.1347x; 1.1347x over previous
#include <cuda_runtime.h>
#include <cuda_bf16.h>
#include <math.h>

// Problem constants
#define TT   4096      // tokens = B*S
#define DD   1024      // model dim
#define HH   1024      // hidden dim
#define EE   16        // experts
#define KK   2         // top-k
#define CAP  640       // capacity = ceil(T*K/E*1.25)
#define CBUF 1280      // K*capacity

// GEMM tiling
#define BM 128
#define BN 64
#define BKD 16
#define NITER (DD / BKD)   // 64 (HH/BKD identical)

typedef unsigned long long ull;

// ---------------- packed f32x2 helpers (Blackwell FFMA2 path) ----------------
__device__ __forceinline__ void ffma2(ull& d, ull a, ull b) {
    asm("fma.rn.f32x2 %0, %1, %2, %3;" : "=l"(d) : "l"(a), "l"(b), "l"(d));
}
__device__ __forceinline__ ull pack2(float x, float y) {
    ull r; asm("mov.b64 %0, {%1, %2};" : "=l"(r) : "f"(x), "f"(y)); return r;
}
__device__ __forceinline__ float2 unpack2(ull v) {
    float2 r; asm("mov.b64 {%0, %1}, %2;" : "=f"(r.x), "=f"(r.y) : "l"(v)); return r;
}

// ---------------- device scratch (no allocations allowed) ----------------
__device__ int   g_topk_idx[TT * KK];
__device__ float g_topk_w[TT * KK];
__device__ int   g_disp_tok[EE * CBUF];
__device__ float g_disp_w[EE * CBUF];
__device__ int   g_count[EE];
__device__ float g_hidden[(size_t)EE * CBUF * HH];   // ~84 MB scratch

// ---------------- kernel 0: zero output ----------------
__global__ void zero_out_kernel(float* __restrict__ out) {
    out[(size_t)blockIdx.x * 1024 + threadIdx.x] = 0.0f;
}

// ---------------- kernel 1: router (GEMV + softmax + top2) ----------------
// one warp per token
__global__ void router_kernel(const float* __restrict__ x,
                              const float* __restrict__ rw) {
    int warp = (blockIdx.x * blockDim.x + threadIdx.x) >> 5;
    int lane = threadIdx.x & 31;
    if (warp >= TT) return;
    const float* xr = x + (size_t)warp * DD;

    float acc[EE];
#pragma unroll
    for (int e = 0; e < EE; e++) acc[e] = 0.0f;

    for (int d = lane; d < DD; d += 32) {
        float xv = __ldg(xr + d);
        const float4* rwp = (const float4*)(rw + (size_t)d * EE);
#pragma unroll
        for (int q = 0; q < 4; q++) {
            float4 v = __ldg(rwp + q);
            acc[4 * q + 0] += xv * v.x;
            acc[4 * q + 1] += xv * v.y;
            acc[4 * q + 2] += xv * v.z;
            acc[4 * q + 3] += xv * v.w;
        }
    }
#pragma unroll
    for (int e = 0; e < EE; e++) {
#pragma unroll
        for (int off = 16; off; off >>= 1)
            acc[e] += __shfl_xor_sync(0xffffffffu, acc[e], off);
    }

    if (lane == 0) {
        // top-2 on logits (softmax monotonic); strict '>' scan matches
        // lax.top_k tie-break (lowest index wins).
        int i1 = 0; float v1 = acc[0];
#pragma unroll
        for (int e = 1; e < EE; e++) if (acc[e] > v1) { v1 = acc[e]; i1 = e; }
        int i2 = -1; float v2 = -1e30f;
#pragma unroll
        for (int e = 0; e < EE; e++) {
            if (e == i1) continue;
            if (acc[e] > v2) { v2 = acc[e]; i2 = e; }
        }
        float mx = v1;
        float s = 0.0f;
#pragma unroll
        for (int e = 0; e < EE; e++) s += expf(acc[e] - mx);
        float w1 = expf(v1 - mx) / s;
        float w2 = expf(v2 - mx) / s;
        g_topk_idx[warp * 2 + 0] = i1;
        g_topk_idx[warp * 2 + 1] = i2;
        g_topk_w[warp * 2 + 0] = w1;
        g_topk_w[warp * 2 + 1] = w2;
    }
}

// ---------------- kernel 2: ordered rank scan + compaction ----------------
__global__ void scan_kernel() {
    __shared__ int cnt[512][EE];     // 32 KB
    __shared__ int ecount[EE];
    int tid = threadIdx.x;
    int k = tid >> 8;
    int c = tid & 255;
    int t0 = c * 16;

#pragma unroll
    for (int e = 0; e < EE; e++) cnt[tid][e] = 0;
    if (tid < EE) ecount[tid] = 0;
    __syncthreads();

    for (int i = 0; i < 16; i++) {
        int e = g_topk_idx[(t0 + i) * 2 + k];
        cnt[tid][e]++;
    }
    __syncthreads();

    if (tid < 32) {
        int kk = tid >> 4, ee = tid & 15;
        int run = 0;
        for (int cc = 0; cc < 256; cc++) {
            int idx = kk * 256 + cc;
            int v = cnt[idx][ee];
            cnt[idx][ee] = run;
            run += v;
        }
    }
    __syncthreads();

    for (int i = 0; i < 16; i++) {
        int t = t0 + i;
        int e = g_topk_idx[t * 2 + k];
        float w = g_topk_w[t * 2 + k];
        int rank = cnt[tid][e]++;
        if (rank < CAP) {
            int slot = atomicAdd(&ecount[e], 1);
            g_disp_tok[e * CBUF + slot] = t;
            g_disp_w[e * CBUF + slot] = w;
        }
    }
    __syncthreads();
    if (tid < EE) g_count[tid] = ecount[tid];
}

// ---------------- kernel 3: fused gate/up GEMM + silu (FFMA2, dbl-buf) ----
__global__ __launch_bounds__(256, 2)
void gemm1_kernel(const float* __restrict__ x,
                  const float* __restrict__ gw,
                  const float* __restrict__ uw) {
    int e  = blockIdx.z;
    int m  = g_count[e];
    int m0 = blockIdx.y * BM;
    if (m0 >= m) return;
    int h0 = blockIdx.x * BN;

    __shared__ float As[2][BKD][BM];
    __shared__ float Bg[2][BKD][BN];
    __shared__ float Bu[2][BKD][BN];

    int tid = threadIdx.x;
    int tx = tid & 15;       // 16 col groups * 4 cols
    int ty = tid >> 4;       // 16 row groups * 8 rows

    // A-load mapping: 2 float4 per thread
    int rowA0 = tid >> 2;            // 0..63
    int rowA1 = rowA0 + 64;
    int c4 = (tid & 3) * 4;
    int tokA0 = (m0 + rowA0 < m) ? g_disp_tok[e * CBUF + m0 + rowA0] : 0;
    int tokA1 = (m0 + rowA1 < m) ? g_disp_tok[e * CBUF + m0 + rowA1] : 0;
    const float* xA0 = x + (size_t)tokA0 * DD + c4;
    const float* xA1 = x + (size_t)tokA1 * DD + c4;

    // B-load mapping: 1 float4 per thread per matrix
    int kb = tid >> 4;               // 0..15
    int hq = (tid & 15) * 4;
    const float* gwe = gw + (size_t)e * DD * HH + (size_t)kb * HH + h0 + hq;
    const float* uwe = uw + (size_t)e * DD * HH + (size_t)kb * HH + h0 + hq;

    // preload tile 0 into buffer 0
    {
        float4 a0 = *(const float4*)(xA0);
        float4 a1 = *(const float4*)(xA1);
        float4 bg = *(const float4*)(gwe);
        float4 bu = *(const float4*)(uwe);
        As[0][c4 + 0][rowA0] = a0.x; As[0][c4 + 1][rowA0] = a0.y;
        As[0][c4 + 2][rowA0] = a0.z; As[0][c4 + 3][rowA0] = a0.w;
        As[0][c4 + 0][rowA1] = a1.x; As[0][c4 + 1][rowA1] = a1.y;
        As[0][c4 + 2][rowA1] = a1.z; As[0][c4 + 3][rowA1] = a1.w;
        *(float4*)&Bg[0][kb][hq] = bg;
        *(float4*)&Bu[0][kb][hq] = bu;
    }
    __syncthreads();

    ull accg[8][2], accu[8][2];
#pragma unroll
    for (int i = 0; i < 8; i++) {
        accg[i][0] = 0ull; accg[i][1] = 0ull;
        accu[i][0] = 0ull; accu[i][1] = 0ull;
    }

    for (int it = 0; it < NITER; it++) {
        int buf = it & 1;
        float4 na0, na1, nbg, nbu;
        bool have_next = (it + 1 < NITER);
        if (have_next) {
            int k0 = (it + 1) * BKD;
            na0 = *(const float4*)(xA0 + k0);
            na1 = *(const float4*)(xA1 + k0);
            nbg = *(const float4*)(gwe + (size_t)k0 * HH);
            nbu = *(const float4*)(uwe + (size_t)k0 * HH);
        }

#pragma unroll
        for (int kk = 0; kk < BKD; kk++) {
            float4 av0 = *(const float4*)&As[buf][kk][ty * 8];
            float4 av1 = *(const float4*)&As[buf][kk][ty * 8 + 4];
            ulonglong2 bg2 = *(const ulonglong2*)&Bg[buf][kk][tx * 4];
            ulonglong2 bu2 = *(const ulonglong2*)&Bu[buf][kk][tx * 4];
            float a[8] = {av0.x, av0.y, av0.z, av0.w, av1.x, av1.y, av1.z, av1.w};
#pragma unroll
            for (int i = 0; i < 8; i++) {
                ull a2 = pack2(a[i], a[i]);
                ffma2(accg[i][0], a2, bg2.x);
                ffma2(accg[i][1], a2, bg2.y);
                ffma2(accu[i][0], a2, bu2.x);
                ffma2(accu[i][1], a2, bu2.y);
            }
        }

        if (have_next) {
            int nb = buf ^ 1;
            As[nb][c4 + 0][rowA0] = na0.x; As[nb][c4 + 1][rowA0] = na0.y;
            As[nb][c4 + 2][rowA0] = na0.z; As[nb][c4 + 3][rowA0] = na0.w;
            As[nb][c4 + 0][rowA1] = na1.x; As[nb][c4 + 1][rowA1] = na1.y;
            As[nb][c4 + 2][rowA1] = na1.z; As[nb][c4 + 3][rowA1] = na1.w;
            *(float4*)&Bg[nb][kb][hq] = nbg;
            *(float4*)&Bu[nb][kb][hq] = nbu;
        }
        __syncthreads();
    }

    // epilogue: hidden = silu(gate) * up
#pragma unroll
    for (int i = 0; i < 8; i++) {
        int gr = m0 + ty * 8 + i;
        if (gr < m) {
            float2 g0 = unpack2(accg[i][0]);
            float2 g1 = unpack2(accg[i][1]);
            float2 u0 = unpack2(accu[i][0]);
            float2 u1 = unpack2(accu[i][1]);
            float4 hv;
            hv.x = (g0.x / (1.0f + expf(-g0.x))) * u0.x;
            hv.y = (g0.y / (1.0f + expf(-g0.y))) * u0.y;
            hv.z = (g1.x / (1.0f + expf(-g1.x))) * u1.x;
            hv.w = (g1.y / (1.0f + expf(-g1.y))) * u1.y;
            *(float4*)&g_hidden[((size_t)e * CBUF + gr) * HH + h0 + tx * 4] = hv;
        }
    }
}

// ---------------- kernel 4: down GEMM + weighted scatter-add (FFMA2) ------
__global__ __launch_bounds__(256, 2)
void gemm2_kernel(const float* __restrict__ dw, float* __restrict__ out) {
    int e  = blockIdx.z;
    int m  = g_count[e];
    int m0 = blockIdx.y * BM;
    if (m0 >= m) return;
    int d0 = blockIdx.x * BN;

    __shared__ float As[2][BKD][BM];
    __shared__ float Bs[2][BKD][BN];

    int tid = threadIdx.x;
    int tx = tid & 15;
    int ty = tid >> 4;

    int rowA0 = tid >> 2;
    int rowA1 = rowA0 + 64;
    int c4 = (tid & 3) * 4;
    const float* hA0 = g_hidden + ((size_t)e * CBUF + m0 + rowA0) * HH + c4;
    const float* hA1 = g_hidden + ((size_t)e * CBUF + m0 + rowA1) * HH + c4;

    int kb = tid >> 4;
    int hq = (tid & 15) * 4;
    const float* dwe = dw + (size_t)e * HH * DD + (size_t)kb * DD + d0 + hq;

    {
        float4 a0 = *(const float4*)(hA0);
        float4 a1 = *(const float4*)(hA1);
        float4 b  = *(const float4*)(dwe);
        As[0][c4 + 0][rowA0] = a0.x; As[0][c4 + 1][rowA0] = a0.y;
        As[0][c4 + 2][rowA0] = a0.z; As[0][c4 + 3][rowA0] = a0.w;
        As[0][c4 + 0][rowA1] = a1.x; As[0][c4 + 1][rowA1] = a1.y;
        As[0][c4 + 2][rowA1] = a1.z; As[0][c4 + 3][rowA1] = a1.w;
        *(float4*)&Bs[0][kb][hq] = b;
    }
    __syncthreads();

    ull acc[8][2];
#pragma unroll
    for (int i = 0; i < 8; i++) { acc[i][0] = 0ull; acc[i][1] = 0ull; }

    for (int it = 0; it < NITER; it++) {
        int buf = it & 1;
        float4 na0, na1, nb4;
        bool have_next = (it + 1 < NITER);
        if (have_next) {
            int k0 = (it + 1) * BKD;
            na0 = *(const float4*)(hA0 + k0);
            na1 = *(const float4*)(hA1 + k0);
            nb4 = *(const float4*)(dwe + (size_t)k0 * DD);
        }

#pragma unroll
        for (int kk = 0; kk < BKD; kk++) {
            float4 av0 = *(const float4*)&As[buf][kk][ty * 8];
            float4 av1 = *(const float4*)&As[buf][kk][ty * 8 + 4];
            ulonglong2 b2 = *(const ulonglong2*)&Bs[buf][kk][tx * 4];
            float a[8] = {av0.x, av0.y, av0.z, av0.w, av1.x, av1.y, av1.z, av1.w};
#pragma unroll
            for (int i = 0; i < 8; i++) {
                ull a2 = pack2(a[i], a[i]);
                ffma2(acc[i][0], a2, b2.x);
                ffma2(acc[i][1], a2, b2.y);
            }
        }

        if (have_next) {
            int nb = buf ^ 1;
            As[nb][c4 + 0][rowA0] = na0.x; As[nb][c4 + 1][rowA0] = na0.y;
            As[nb][c4 + 2][rowA0] = na0.z; As[nb][c4 + 3][rowA0] = na0.w;
            As[nb][c4 + 0][rowA1] = na1.x; As[nb][c4 + 1][rowA1] = na1.y;
            As[nb][c4 + 2][rowA1] = na1.z; As[nb][c4 + 3][rowA1] = na1.w;
            *(float4*)&Bs[nb][kb][hq] = nb4;
        }
        __syncthreads();
    }

    // epilogue: scale by gate weight, scatter-add to token row
#pragma unroll
    for (int i = 0; i < 8; i++) {
        int gr = m0 + ty * 8 + i;
        if (gr < m) {
            int tok = g_disp_tok[e * CBUF + gr];
            float w = g_disp_w[e * CBUF + gr];
            float2 v0 = unpack2(acc[i][0]);
            float2 v1 = unpack2(acc[i][1]);
            float* op = out + (size_t)tok * DD + d0 + tx * 4;
            atomicAdd(op + 0, v0.x * w);
            atomicAdd(op + 1, v0.y * w);
            atomicAdd(op + 2, v1.x * w);
            atomicAdd(op + 3, v1.y * w);
        }
    }
}

// ---------------- launcher ----------------
extern "C" void kernel_launch(void* const* d_in, const int* in_sizes, int n_in,
                              void* d_out, int out_size) {
    const float* x  = (const float*)d_in[0];
    const float* rw = (const float*)d_in[1];
    const float* gw = (const float*)d_in[2];
    const float* uw = (const float*)d_in[3];
    const float* dw = (const float*)d_in[4];
    float* out = (float*)d_out;

    zero_out_kernel<<<TT, 1024>>>(out);
    router_kernel<<<TT / 8, 256>>>(x, rw);
    scan_kernel<<<1, 512>>>();
    gemm1_kernel<<<dim3(HH / BN, CBUF / BM, EE), 256>>>(x, gw, uw);
    gemm2_kernel<<<dim3(DD / BN, CBUF / BM, EE), 256>>>(dw, out);
}

// round 10
// speedup vs baseline: 1.6297x; 1.4362x over previous
#include <cuda_runtime.h>
#include <cuda_bf16.h>
#include <math.h>
#include <stdint.h>

// Problem constants
#define TT   4096      // tokens = B*S
#define DD   1024      // model dim
#define HH   1024      // hidden dim
#define EE   16        // experts
#define KK   2         // top-k
#define CAP  640       // capacity
#define CBUF 1280      // K*capacity

// GEMM tiling
#define BM    128      // token rows per block
#define BK    32       // K elements per smem chunk (bf16)
#define NCH   32       // 1024 / 32 chunks
#define ROWB  80       // padded smem row stride bytes (32*2 + 16)
#define ROWU  20       // row stride in u32 words

// gemm1 smem layout (static, 40960 B total)
#define S1_AH 0
#define S1_AL 10240
#define S1_B  20480    // 4 tiles x 5120: gate_hi, gate_lo, up_hi, up_lo
// gemm2 smem layout (static, 30720 B total)
#define S2_AH 0
#define S2_AL 10240
#define S2_BH 20480
#define S2_BL 25600

// ---------------- mma.sync (only inline asm) ----------------
__device__ __forceinline__ void mma_bf16(float* c, const uint32_t* a, const uint32_t* b) {
    asm volatile("mma.sync.aligned.m16n8k16.row.col.f32.bf16.bf16.f32 "
                 "{%0,%1,%2,%3}, {%4,%5,%6,%7}, {%8,%9}, {%0,%1,%2,%3};"
                 : "+f"(c[0]), "+f"(c[1]), "+f"(c[2]), "+f"(c[3])
                 : "r"(a[0]), "r"(a[1]), "r"(a[2]), "r"(a[3]), "r"(b[0]), "r"(b[1]));
}

// ---------------- device scratch ----------------
__device__ int   g_topk_idx[TT * KK];
__device__ float g_topk_w[TT * KK];
__device__ int   g_disp_tok[EE * CBUF];
__device__ float g_disp_w[EE * CBUF];
__device__ int   g_count[EE];

__device__ __align__(16) __nv_bfloat16 g_xhi[(size_t)TT * DD];
__device__ __align__(16) __nv_bfloat16 g_xlo[(size_t)TT * DD];
__device__ __align__(16) __nv_bfloat16 g_gwThi[(size_t)EE * HH * DD];  // [E][H][D]
__device__ __align__(16) __nv_bfloat16 g_gwTlo[(size_t)EE * HH * DD];
__device__ __align__(16) __nv_bfloat16 g_uwThi[(size_t)EE * HH * DD];
__device__ __align__(16) __nv_bfloat16 g_uwTlo[(size_t)EE * HH * DD];
__device__ __align__(16) __nv_bfloat16 g_dwThi[(size_t)EE * DD * HH];  // [E][D][H]
__device__ __align__(16) __nv_bfloat16 g_dwTlo[(size_t)EE * DD * HH];
__device__ __align__(16) __nv_bfloat16 g_hidhi[(size_t)EE * CBUF * HH];
__device__ __align__(16) __nv_bfloat16 g_hidlo[(size_t)EE * CBUF * HH];

// ---------------- kernel 0: zero output ----------------
__global__ void zero_out_kernel(float* __restrict__ out) {
    out[(size_t)blockIdx.x * 1024 + threadIdx.x] = 0.0f;
}

// ---------------- kernel 1: router (verbatim from passing R4) -------------
__global__ void router_kernel(const float* __restrict__ x,
                              const float* __restrict__ rw) {
    int warp = (blockIdx.x * blockDim.x + threadIdx.x) >> 5;
    int lane = threadIdx.x & 31;
    if (warp >= TT) return;
    const float* xr = x + (size_t)warp * DD;

    float acc[EE];
#pragma unroll
    for (int e = 0; e < EE; e++) acc[e] = 0.0f;
    for (int d = lane; d < DD; d += 32) {
        float xv = __ldg(xr + d);
        const float4* rwp = (const float4*)(rw + (size_t)d * EE);
#pragma unroll
        for (int q = 0; q < 4; q++) {
            float4 v = __ldg(rwp + q);
            acc[4 * q + 0] += xv * v.x;
            acc[4 * q + 1] += xv * v.y;
            acc[4 * q + 2] += xv * v.z;
            acc[4 * q + 3] += xv * v.w;
        }
    }
#pragma unroll
    for (int e = 0; e < EE; e++) {
#pragma unroll
        for (int off = 16; off; off >>= 1)
            acc[e] += __shfl_xor_sync(0xffffffffu, acc[e], off);
    }
    if (lane == 0) {
        int i1 = 0; float v1 = acc[0];
#pragma unroll
        for (int e = 1; e < EE; e++) if (acc[e] > v1) { v1 = acc[e]; i1 = e; }
        int i2 = -1; float v2 = -1e30f;
#pragma unroll
        for (int e = 0; e < EE; e++) {
            if (e == i1) continue;
            if (acc[e] > v2) { v2 = acc[e]; i2 = e; }
        }
        float mx = v1;
        float s = 0.0f;
#pragma unroll
        for (int e = 0; e < EE; e++) s += expf(acc[e] - mx);
        float w1 = expf(v1 - mx) / s;
        float w2 = expf(v2 - mx) / s;
        g_topk_idx[warp * 2 + 0] = i1;
        g_topk_idx[warp * 2 + 1] = i2;
        g_topk_w[warp * 2 + 0] = w1;
        g_topk_w[warp * 2 + 1] = w2;
    }
}

// ---------------- kernel 2: ordered rank scan + compaction (verbatim) -----
__global__ void scan_kernel() {
    __shared__ int cnt[512][EE];
    __shared__ int ecount[EE];
    int tid = threadIdx.x;
    int k = tid >> 8;
    int c = tid & 255;
    int t0 = c * 16;

#pragma unroll
    for (int e = 0; e < EE; e++) cnt[tid][e] = 0;
    if (tid < EE) ecount[tid] = 0;
    __syncthreads();

    for (int i = 0; i < 16; i++) {
        int e = g_topk_idx[(t0 + i) * 2 + k];
        cnt[tid][e]++;
    }
    __syncthreads();

    if (tid < 32) {
        int kk = tid >> 4, ee = tid & 15;
        int run = 0;
        for (int cc = 0; cc < 256; cc++) {
            int idx = kk * 256 + cc;
            int v = cnt[idx][ee];
            cnt[idx][ee] = run;
            run += v;
        }
    }
    __syncthreads();

    for (int i = 0; i < 16; i++) {
        int t = t0 + i;
        int e = g_topk_idx[t * 2 + k];
        float w = g_topk_w[t * 2 + k];
        int rank = cnt[tid][e]++;
        if (rank < CAP) {
            int slot = atomicAdd(&ecount[e], 1);
            g_disp_tok[e * CBUF + slot] = t;
            g_disp_w[e * CBUF + slot] = w;
        }
    }
    __syncthreads();
    if (tid < EE) g_count[tid] = ecount[tid];
}

// ---------------- kernel 3: split x into bf16 hi/lo ----------------
__global__ void split_x_kernel(const float* __restrict__ x) {
    size_t i = ((size_t)blockIdx.x * 256 + threadIdx.x) * 4;
    float4 v = *(const float4*)(x + i);
    float f[4] = {v.x, v.y, v.z, v.w};
#pragma unroll
    for (int j = 0; j < 4; j += 2) {
        __nv_bfloat16 h0 = __float2bfloat16_rn(f[j]);
        __nv_bfloat16 h1 = __float2bfloat16_rn(f[j + 1]);
        __nv_bfloat16 l0 = __float2bfloat16_rn(f[j] - __bfloat162float(h0));
        __nv_bfloat16 l1 = __float2bfloat16_rn(f[j + 1] - __bfloat162float(h1));
        __nv_bfloat162 vh; vh.x = h0; vh.y = h1;
        __nv_bfloat162 vl; vl.x = l0; vl.y = l1;
        *(__nv_bfloat162*)(g_xhi + i + j) = vh;
        *(__nv_bfloat162*)(g_xlo + i + j) = vl;
    }
}

// ---------------- kernel 4: transpose + split weights ----------------
// src [E][R=1024][C=1024] fp32 -> dst [E][C][R] bf16 hi/lo.
// FIX (R9): destination selected INSIDE device code via `which` — passing
// __device__ globals as host-side kernel args gives the host shadow symbol
// address (invalid on device), which silently nulled all weights in R6-R8.
__global__ void trans_split_kernel(const float* __restrict__ src, int which) {
    __nv_bfloat16* dhi = (which == 0) ? g_gwThi : (which == 1) ? g_uwThi : g_dwThi;
    __nv_bfloat16* dlo = (which == 0) ? g_gwTlo : (which == 1) ? g_uwTlo : g_dwTlo;

    __shared__ float tile[32][33];
    int e  = blockIdx.z;
    int r0 = blockIdx.y * 32;
    int c0 = blockIdx.x * 32;
    int tx = threadIdx.x, ty = threadIdx.y;   // 32 x 8
    const float* s = src + ((size_t)e * 1024 + r0) * 1024 + c0;
#pragma unroll
    for (int j = 0; j < 4; j++)
        tile[ty + 8 * j][tx] = s[(size_t)(ty + 8 * j) * 1024 + tx];
    __syncthreads();
    int t = ty * 32 + tx;
    int r2 = t & 15;
    int cl = t >> 4;
#pragma unroll
    for (int p = 0; p < 2; p++) {
        int c = cl + p * 16;
        float a = tile[r2 * 2][c], b = tile[r2 * 2 + 1][c];
        __nv_bfloat16 ah = __float2bfloat16_rn(a), bh = __float2bfloat16_rn(b);
        __nv_bfloat16 al = __float2bfloat16_rn(a - __bfloat162float(ah));
        __nv_bfloat16 bl = __float2bfloat16_rn(b - __bfloat162float(bh));
        size_t o = ((size_t)e * 1024 + c0 + c) * 1024 + r0 + r2 * 2;
        __nv_bfloat162 vh; vh.x = ah; vh.y = bh;
        __nv_bfloat162 vl; vl.x = al; vl.y = bl;
        *(__nv_bfloat162*)(dhi + o) = vh;
        *(__nv_bfloat162*)(dlo + o) = vl;
    }
}

// ---------------- kernel 5: gemm1 (mma.sync bf16x3, explicit LDS frags) ---
__global__ __launch_bounds__(256, 2)
void gemm1_kernel() {
    int e    = blockIdx.z;
    int mcnt = g_count[e];
    mcnt = (mcnt < 0) ? 0 : ((mcnt > CBUF) ? CBUF : mcnt);
    int m0   = blockIdx.y * BM;
    if (m0 >= mcnt) return;
    int h0 = blockIdx.x * 64;

    __shared__ __align__(16) unsigned char sm[40960];
    __shared__ int s_tok[BM];

    int tid  = threadIdx.x;
    int lane = tid & 31;
    int w    = tid >> 5;
    int mat  = w >> 2;        // 0 = gate, 1 = up
    int wm   = (w >> 1) & 1;  // m half (64 rows)
    int wn   = w & 1;         // n half (32 cols)

    if (tid < BM) {
        int gr = m0 + tid;
        int tk = (gr < mcnt) ? g_disp_tok[e * CBUF + gr] : -1;
        if (tk < 0 || tk >= TT) tk = (gr < mcnt) ? 0 : -1;
        s_tok[tid] = tk;
    }
    __syncthreads();

    int rowA0 = tid >> 2;              // rows 0..63
    int rowA1 = rowA0 + 64;            // rows 64..127
    int c8 = tid & 3;
    int tokA0 = s_tok[rowA0];
    int tokA1 = s_tok[rowA1];
    int rowB = tid >> 2;               // 0..63

    float acc[4][4][4];
#pragma unroll
    for (int im = 0; im < 4; im++)
#pragma unroll
        for (int in = 0; in < 4; in++)
#pragma unroll
            for (int r = 0; r < 4; r++) acc[im][in][r] = 0.0f;

    const uint4 zero4 = {0, 0, 0, 0};
    int g = lane >> 2, q = lane & 3;
    const uint32_t* Ah32 = (const uint32_t*)(sm + S1_AH);
    const uint32_t* Al32 = (const uint32_t*)(sm + S1_AL);
    const uint32_t* BgH  = (const uint32_t*)(sm + S1_B + (size_t)mat * 10240);
    const uint32_t* BgL  = (const uint32_t*)(sm + S1_B + (size_t)mat * 10240 + 5120);

    for (int ch = 0; ch < NCH; ch++) {
        int k0 = ch * BK;
        {
            size_t a0 = (size_t)(tokA0 < 0 ? 0 : tokA0) * DD + k0 + c8 * 8;
            size_t a1 = (size_t)(tokA1 < 0 ? 0 : tokA1) * DD + k0 + c8 * 8;
            uint4 h0v = (tokA0 >= 0) ? *(const uint4*)(g_xhi + a0) : zero4;
            uint4 l0v = (tokA0 >= 0) ? *(const uint4*)(g_xlo + a0) : zero4;
            uint4 h1v = (tokA1 >= 0) ? *(const uint4*)(g_xhi + a1) : zero4;
            uint4 l1v = (tokA1 >= 0) ? *(const uint4*)(g_xlo + a1) : zero4;
            size_t bb = ((size_t)e * HH + h0 + rowB) * DD + k0 + c8 * 8;
            uint4 bgh = *(const uint4*)(g_gwThi + bb);
            uint4 bgl = *(const uint4*)(g_gwTlo + bb);
            uint4 buh = *(const uint4*)(g_uwThi + bb);
            uint4 bul = *(const uint4*)(g_uwTlo + bb);
            *(uint4*)(sm + S1_AH + rowA0 * ROWB + c8 * 16) = h0v;
            *(uint4*)(sm + S1_AL + rowA0 * ROWB + c8 * 16) = l0v;
            *(uint4*)(sm + S1_AH + rowA1 * ROWB + c8 * 16) = h1v;
            *(uint4*)(sm + S1_AL + rowA1 * ROWB + c8 * 16) = l1v;
            *(uint4*)(sm + S1_B + 0     + rowB * ROWB + c8 * 16) = bgh;
            *(uint4*)(sm + S1_B + 5120  + rowB * ROWB + c8 * 16) = bgl;
            *(uint4*)(sm + S1_B + 10240 + rowB * ROWB + c8 * 16) = buh;
            *(uint4*)(sm + S1_B + 15360 + rowB * ROWB + c8 * 16) = bul;
        }
        __syncthreads();

#pragma unroll
        for (int ks = 0; ks < 2; ks++) {
            int kc = ks * 8;
            uint32_t Bh[4][2], Bl[4][2];
#pragma unroll
            for (int in = 0; in < 4; in++) {
                int r = wn * 32 + in * 8 + g;
                Bh[in][0] = BgH[r * ROWU + kc + q];
                Bh[in][1] = BgH[r * ROWU + kc + 4 + q];
                Bl[in][0] = BgL[r * ROWU + kc + q];
                Bl[in][1] = BgL[r * ROWU + kc + 4 + q];
            }
#pragma unroll
            for (int im = 0; im < 4; im++) {
                int r0 = wm * 64 + im * 16 + g;
                uint32_t Af[4], Lf[4];
                Af[0] = Ah32[r0 * ROWU + kc + q];
                Af[1] = Ah32[(r0 + 8) * ROWU + kc + q];
                Af[2] = Ah32[r0 * ROWU + kc + 4 + q];
                Af[3] = Ah32[(r0 + 8) * ROWU + kc + 4 + q];
                Lf[0] = Al32[r0 * ROWU + kc + q];
                Lf[1] = Al32[(r0 + 8) * ROWU + kc + q];
                Lf[2] = Al32[r0 * ROWU + kc + 4 + q];
                Lf[3] = Al32[(r0 + 8) * ROWU + kc + 4 + q];
#pragma unroll
                for (int in = 0; in < 4; in++) {
                    mma_bf16(acc[im][in], Af, Bh[in]);
                    mma_bf16(acc[im][in], Af, Bl[in]);
                    mma_bf16(acc[im][in], Lf, Bh[in]);
                }
            }
        }
        __syncthreads();
    }

    // ---- epilogue: up warps stage to smem; gate warps fuse silu(g)*u ----
    float* ex = (float*)sm;   // 128 x 64 fp32 = 32 KB
    if (mat == 1) {
#pragma unroll
        for (int im = 0; im < 4; im++)
#pragma unroll
            for (int in = 0; in < 4; in++) {
                int rb = wm * 64 + im * 16 + g;
                int nb = wn * 32 + in * 8 + q * 2;
                ex[rb * 64 + nb]           = acc[im][in][0];
                ex[rb * 64 + nb + 1]       = acc[im][in][1];
                ex[(rb + 8) * 64 + nb]     = acc[im][in][2];
                ex[(rb + 8) * 64 + nb + 1] = acc[im][in][3];
            }
    }
    __syncthreads();
    if (mat == 0) {
#pragma unroll
        for (int im = 0; im < 4; im++)
#pragma unroll
            for (int in = 0; in < 4; in++) {
                int rb = wm * 64 + im * 16 + g;
                int nb = wn * 32 + in * 8 + q * 2;
#pragma unroll
                for (int h = 0; h < 2; h++) {
                    int r = rb + h * 8;
                    int gr = m0 + r;
                    if (gr < mcnt) {
                        float g0 = acc[im][in][h * 2], g1 = acc[im][in][h * 2 + 1];
                        float u0 = ex[r * 64 + nb], u1 = ex[r * 64 + nb + 1];
                        float f0 = (g0 / (1.0f + expf(-g0))) * u0;
                        float f1 = (g1 / (1.0f + expf(-g1))) * u1;
                        __nv_bfloat16 h0b = __float2bfloat16_rn(f0);
                        __nv_bfloat16 h1b = __float2bfloat16_rn(f1);
                        __nv_bfloat16 l0b = __float2bfloat16_rn(f0 - __bfloat162float(h0b));
                        __nv_bfloat16 l1b = __float2bfloat16_rn(f1 - __bfloat162float(h1b));
                        size_t o = ((size_t)e * CBUF + gr) * HH + h0 + nb;
                        __nv_bfloat162 vh; vh.x = h0b; vh.y = h1b;
                        __nv_bfloat162 vl; vl.x = l0b; vl.y = l1b;
                        *(__nv_bfloat162*)(g_hidhi + o) = vh;
                        *(__nv_bfloat162*)(g_hidlo + o) = vl;
                    }
                }
            }
    }
}

// ---------------- kernel 6: gemm2 (mma.sync bf16x3, down) + scatter-add ---
__global__ __launch_bounds__(256, 2)
void gemm2_kernel(float* __restrict__ out) {
    int e    = blockIdx.z;
    int mcnt = g_count[e];
    mcnt = (mcnt < 0) ? 0 : ((mcnt > CBUF) ? CBUF : mcnt);
    int m0   = blockIdx.y * BM;
    if (m0 >= mcnt) return;
    int d0 = blockIdx.x * 64;

    __shared__ __align__(16) unsigned char sm[30720];
    __shared__ int   s_tok[BM];
    __shared__ float s_w[BM];

    int tid  = threadIdx.x;
    int lane = tid & 31;
    int w    = tid >> 5;
    int wm   = w >> 1;   // 0..3
    int wn   = w & 1;    // 0..1

    if (tid < BM) {
        int gr = m0 + tid;
        bool v = gr < mcnt;
        int tk = v ? g_disp_tok[e * CBUF + gr] : 0;
        if (tk < 0 || tk >= TT) tk = 0;
        s_tok[tid] = tk;
        s_w[tid]   = v ? g_disp_w[e * CBUF + gr] : 0.0f;
    }
    __syncthreads();

    int rowA0 = tid >> 2;
    int rowA1 = rowA0 + 64;
    int c8 = tid & 3;
    bool vA0 = (m0 + rowA0) < mcnt;
    bool vA1 = (m0 + rowA1) < mcnt;
    int rowB = tid >> 2;

    float acc[2][4][4];
#pragma unroll
    for (int im = 0; im < 2; im++)
#pragma unroll
        for (int in = 0; in < 4; in++)
#pragma unroll
            for (int r = 0; r < 4; r++) acc[im][in][r] = 0.0f;

    const uint4 zero4 = {0, 0, 0, 0};
    int g = lane >> 2, q = lane & 3;
    const uint32_t* Ah32 = (const uint32_t*)(sm + S2_AH);
    const uint32_t* Al32 = (const uint32_t*)(sm + S2_AL);
    const uint32_t* Bh32 = (const uint32_t*)(sm + S2_BH);
    const uint32_t* Bl32 = (const uint32_t*)(sm + S2_BL);

    for (int ch = 0; ch < NCH; ch++) {
        int k0 = ch * BK;
        {
            size_t a0 = ((size_t)e * CBUF + (vA0 ? m0 + rowA0 : 0)) * HH + k0 + c8 * 8;
            size_t a1 = ((size_t)e * CBUF + (vA1 ? m0 + rowA1 : 0)) * HH + k0 + c8 * 8;
            uint4 h0v = vA0 ? *(const uint4*)(g_hidhi + a0) : zero4;
            uint4 l0v = vA0 ? *(const uint4*)(g_hidlo + a0) : zero4;
            uint4 h1v = vA1 ? *(const uint4*)(g_hidhi + a1) : zero4;
            uint4 l1v = vA1 ? *(const uint4*)(g_hidlo + a1) : zero4;
            size_t bb = ((size_t)e * DD + d0 + rowB) * HH + k0 + c8 * 8;
            uint4 bh = *(const uint4*)(g_dwThi + bb);
            uint4 bl = *(const uint4*)(g_dwTlo + bb);
            *(uint4*)(sm + S2_AH + rowA0 * ROWB + c8 * 16) = h0v;
            *(uint4*)(sm + S2_AL + rowA0 * ROWB + c8 * 16) = l0v;
            *(uint4*)(sm + S2_AH + rowA1 * ROWB + c8 * 16) = h1v;
            *(uint4*)(sm + S2_AL + rowA1 * ROWB + c8 * 16) = l1v;
            *(uint4*)(sm + S2_BH + rowB * ROWB + c8 * 16) = bh;
            *(uint4*)(sm + S2_BL + rowB * ROWB + c8 * 16) = bl;
        }
        __syncthreads();

#pragma unroll
        for (int ks = 0; ks < 2; ks++) {
            int kc = ks * 8;
            uint32_t Bh[4][2], Bl[4][2];
#pragma unroll
            for (int in = 0; in < 4; in++) {
                int r = wn * 32 + in * 8 + g;
                Bh[in][0] = Bh32[r * ROWU + kc + q];
                Bh[in][1] = Bh32[r * ROWU + kc + 4 + q];
                Bl[in][0] = Bl32[r * ROWU + kc + q];
                Bl[in][1] = Bl32[r * ROWU + kc + 4 + q];
            }
#pragma unroll
            for (int im = 0; im < 2; im++) {
                int r0 = wm * 32 + im * 16 + g;
                uint32_t Af[4], Lf[4];
                Af[0] = Ah32[r0 * ROWU + kc + q];
                Af[1] = Ah32[(r0 + 8) * ROWU + kc + q];
                Af[2] = Ah32[r0 * ROWU + kc + 4 + q];
                Af[3] = Ah32[(r0 + 8) * ROWU + kc + 4 + q];
                Lf[0] = Al32[r0 * ROWU + kc + q];
                Lf[1] = Al32[(r0 + 8) * ROWU + kc + q];
                Lf[2] = Al32[r0 * ROWU + kc + 4 + q];
                Lf[3] = Al32[(r0 + 8) * ROWU + kc + 4 + q];
#pragma unroll
                for (int in = 0; in < 4; in++) {
                    mma_bf16(acc[im][in], Af, Bh[in]);
                    mma_bf16(acc[im][in], Af, Bl[in]);
                    mma_bf16(acc[im][in], Lf, Bh[in]);
                }
            }
        }
        __syncthreads();
    }

    // epilogue: weighted scatter-add into output
#pragma unroll
    for (int im = 0; im < 2; im++)
#pragma unroll
        for (int in = 0; in < 4; in++) {
            int rb = wm * 32 + im * 16 + g;
            int nb = wn * 32 + in * 8 + q * 2;
#pragma unroll
            for (int h = 0; h < 2; h++) {
                int r = rb + h * 8;
                int gr = m0 + r;
                if (gr < mcnt) {
                    float wt = s_w[r];
                    float* op = out + (size_t)s_tok[r] * DD + d0 + nb;
                    atomicAdd(op + 0, acc[im][in][h * 2] * wt);
                    atomicAdd(op + 1, acc[im][in][h * 2 + 1] * wt);
                }
            }
        }
}

// ---------------- launcher ----------------
extern "C" void kernel_launch(void* const* d_in, const int* in_sizes, int n_in,
                              void* d_out, int out_size) {
    const float* x  = (const float*)d_in[0];
    const float* rw = (const float*)d_in[1];
    const float* gw = (const float*)d_in[2];
    const float* uw = (const float*)d_in[3];
    const float* dw = (const float*)d_in[4];
    float* out = (float*)d_out;

    zero_out_kernel<<<TT, 1024>>>(out);
    split_x_kernel<<<TT, 256>>>(x);
    {
        dim3 tb(32, 8), tg(32, 32, EE);
        trans_split_kernel<<<tg, tb>>>(gw, 0);
        trans_split_kernel<<<tg, tb>>>(uw, 1);
        trans_split_kernel<<<tg, tb>>>(dw, 2);
    }
    router_kernel<<<TT / 8, 256>>>(x, rw);
    scan_kernel<<<1, 512>>>();
    gemm1_kernel<<<dim3(HH / 64, CBUF / BM, EE), 256>>>();
    gemm2_kernel<<<dim3(DD / 64, CBUF / BM, EE), 256>>>(out);
}

// round 11
// speedup vs baseline: 1.7042x; 1.0457x over previous
#include <cuda_runtime.h>
#include <cuda_bf16.h>
#include <math.h>
#include <stdint.h>

// Problem constants
#define TT   4096      // tokens = B*S
#define DD   1024      // model dim
#define HH   1024      // hidden dim
#define EE   16        // experts
#define KK   2         // top-k
#define CAP  640       // capacity
#define CBUF 1280      // K*capacity

// GEMM tiling
#define BM    128      // token rows per block
#define BK    32       // K elements per smem chunk (bf16)
#define NCH   32       // 1024 / 32 chunks
#define ROWB  80       // padded smem row stride bytes (32*2 + 16)
#define ROWU  20       // row stride in u32 words

// gemm1 smem layout (static, 40960 B total)
#define S1_AH 0
#define S1_AL 10240
#define S1_B  20480    // 4 tiles x 5120: gate_hi, gate_lo, up_hi, up_lo
// gemm2 smem layout (static, 30720 B total)
#define S2_AH 0
#define S2_AL 10240
#define S2_BH 20480
#define S2_BL 25600

// ---------------- PTX helpers ----------------
__device__ __forceinline__ uint32_t smem_u32(const void* p) {
    uint32_t a;
    asm("{ .reg .u64 t; cvta.to.shared.u64 t, %1; cvt.u32.u64 %0, t; }" : "=r"(a) : "l"(p));
    return a;
}
__device__ __forceinline__ void ldmx4(uint32_t* r, uint32_t a) {
    asm volatile("ldmatrix.sync.aligned.m8n8.x4.shared.b16 {%0,%1,%2,%3}, [%4];"
                 : "=r"(r[0]), "=r"(r[1]), "=r"(r[2]), "=r"(r[3]) : "r"(a));
}
__device__ __forceinline__ void ldmx2(uint32_t* r, uint32_t a) {
    asm volatile("ldmatrix.sync.aligned.m8n8.x2.shared.b16 {%0,%1}, [%2];"
                 : "=r"(r[0]), "=r"(r[1]) : "r"(a));
}
__device__ __forceinline__ void mma_bf16(float* c, const uint32_t* a, const uint32_t* b) {
    asm volatile("mma.sync.aligned.m16n8k16.row.col.f32.bf16.bf16.f32 "
                 "{%0,%1,%2,%3}, {%4,%5,%6,%7}, {%8,%9}, {%0,%1,%2,%3};"
                 : "+f"(c[0]), "+f"(c[1]), "+f"(c[2]), "+f"(c[3])
                 : "r"(a[0]), "r"(a[1]), "r"(a[2]), "r"(a[3]), "r"(b[0]), "r"(b[1]));
}

// ---------------- device scratch ----------------
__device__ int   g_topk_idx[TT * KK];
__device__ float g_topk_w[TT * KK];
__device__ int   g_disp_tok[EE * CBUF];
__device__ float g_disp_w[EE * CBUF];
__device__ int   g_count[EE];

__device__ __align__(16) __nv_bfloat16 g_xhi[(size_t)TT * DD];
__device__ __align__(16) __nv_bfloat16 g_xlo[(size_t)TT * DD];
__device__ __align__(16) __nv_bfloat16 g_gwThi[(size_t)EE * HH * DD];  // [E][H][D]
__device__ __align__(16) __nv_bfloat16 g_gwTlo[(size_t)EE * HH * DD];
__device__ __align__(16) __nv_bfloat16 g_uwThi[(size_t)EE * HH * DD];
__device__ __align__(16) __nv_bfloat16 g_uwTlo[(size_t)EE * HH * DD];
__device__ __align__(16) __nv_bfloat16 g_dwThi[(size_t)EE * DD * HH];  // [E][D][H]
__device__ __align__(16) __nv_bfloat16 g_dwTlo[(size_t)EE * DD * HH];
__device__ __align__(16) __nv_bfloat16 g_hidhi[(size_t)EE * CBUF * HH];
__device__ __align__(16) __nv_bfloat16 g_hidlo[(size_t)EE * CBUF * HH];

// ---------------- kernel 0: fused prep (weight transpose+split, x split) --
// grid (32, 32, 49), block (32, 8).
// z in [0,48): transpose+split weight tensor (z>>4 selects gw/uw/dw, z&15 = e)
// z == 48:     split x into bf16 hi/lo (block id = by*32+bx, 16 floats/thread)
__global__ void prep_kernel(const float* __restrict__ x,
                            const float* __restrict__ gw,
                            const float* __restrict__ uw,
                            const float* __restrict__ dw) {
    int z = blockIdx.z;
    int tx = threadIdx.x, ty = threadIdx.y;
    if (z < 48) {
        int which = z >> 4;
        int e = z & 15;
        const float* srcw = (which == 0) ? gw : (which == 1) ? uw : dw;
        __nv_bfloat16* dhi = (which == 0) ? g_gwThi : (which == 1) ? g_uwThi : g_dwThi;
        __nv_bfloat16* dlo = (which == 0) ? g_gwTlo : (which == 1) ? g_uwTlo : g_dwTlo;

        __shared__ float tile[32][33];
        int r0 = blockIdx.y * 32;
        int c0 = blockIdx.x * 32;
        const float* s = srcw + ((size_t)e * 1024 + r0) * 1024 + c0;
#pragma unroll
        for (int j = 0; j < 4; j++)
            tile[ty + 8 * j][tx] = s[(size_t)(ty + 8 * j) * 1024 + tx];
        __syncthreads();
        int t = ty * 32 + tx;
        int r2 = t & 15;
        int cl = t >> 4;
#pragma unroll
        for (int p = 0; p < 2; p++) {
            int c = cl + p * 16;
            float a = tile[r2 * 2][c], b = tile[r2 * 2 + 1][c];
            __nv_bfloat16 ah = __float2bfloat16_rn(a), bh = __float2bfloat16_rn(b);
            __nv_bfloat16 al = __float2bfloat16_rn(a - __bfloat162float(ah));
            __nv_bfloat16 bl = __float2bfloat16_rn(b - __bfloat162float(bh));
            size_t o = ((size_t)e * 1024 + c0 + c) * 1024 + r0 + r2 * 2;
            __nv_bfloat162 vh; vh.x = ah; vh.y = bh;
            __nv_bfloat162 vl; vl.x = al; vl.y = bl;
            *(__nv_bfloat162*)(dhi + o) = vh;
            *(__nv_bfloat162*)(dlo + o) = vl;
        }
    } else {
        int b = blockIdx.y * 32 + blockIdx.x;     // 0..1023
        int t = ty * 32 + tx;                     // 0..255
        size_t base = ((size_t)b * 256 + t) * 16; // 16 floats per thread
#pragma unroll
        for (int v = 0; v < 4; v++) {
            size_t i = base + v * 4;
            float4 f4 = *(const float4*)(x + i);
            float f[4] = {f4.x, f4.y, f4.z, f4.w};
#pragma unroll
            for (int j = 0; j < 4; j += 2) {
                __nv_bfloat16 h0 = __float2bfloat16_rn(f[j]);
                __nv_bfloat16 h1 = __float2bfloat16_rn(f[j + 1]);
                __nv_bfloat16 l0 = __float2bfloat16_rn(f[j] - __bfloat162float(h0));
                __nv_bfloat16 l1 = __float2bfloat16_rn(f[j + 1] - __bfloat162float(h1));
                __nv_bfloat162 vh; vh.x = h0; vh.y = h1;
                __nv_bfloat162 vl; vl.x = l0; vl.y = l1;
                *(__nv_bfloat162*)(g_xhi + i + j) = vh;
                *(__nv_bfloat162*)(g_xlo + i + j) = vl;
            }
        }
    }
}

// ---------------- kernel 1: router (+ fused output zeroing) ---------------
__global__ void router_kernel(const float* __restrict__ x,
                              const float* __restrict__ rw,
                              float* __restrict__ out) {
    // fused zero of out: 512 blocks * 256 threads * 32 floats = TT*DD
    {
        size_t zb = ((size_t)(blockIdx.x * blockDim.x + threadIdx.x)) * 32;
        const float4 z4 = {0.0f, 0.0f, 0.0f, 0.0f};
#pragma unroll
        for (int j = 0; j < 8; j++) *(float4*)(out + zb + j * 4) = z4;
    }

    int warp = (blockIdx.x * blockDim.x + threadIdx.x) >> 5;
    int lane = threadIdx.x & 31;
    if (warp >= TT) return;
    const float* xr = x + (size_t)warp * DD;

    float acc[EE];
#pragma unroll
    for (int e = 0; e < EE; e++) acc[e] = 0.0f;
    for (int d = lane; d < DD; d += 32) {
        float xv = __ldg(xr + d);
        const float4* rwp = (const float4*)(rw + (size_t)d * EE);
#pragma unroll
        for (int q = 0; q < 4; q++) {
            float4 v = __ldg(rwp + q);
            acc[4 * q + 0] += xv * v.x;
            acc[4 * q + 1] += xv * v.y;
            acc[4 * q + 2] += xv * v.z;
            acc[4 * q + 3] += xv * v.w;
        }
    }
#pragma unroll
    for (int e = 0; e < EE; e++) {
#pragma unroll
        for (int off = 16; off; off >>= 1)
            acc[e] += __shfl_xor_sync(0xffffffffu, acc[e], off);
    }
    if (lane == 0) {
        int i1 = 0; float v1 = acc[0];
#pragma unroll
        for (int e = 1; e < EE; e++) if (acc[e] > v1) { v1 = acc[e]; i1 = e; }
        int i2 = -1; float v2 = -1e30f;
#pragma unroll
        for (int e = 0; e < EE; e++) {
            if (e == i1) continue;
            if (acc[e] > v2) { v2 = acc[e]; i2 = e; }
        }
        float mx = v1;
        float s = 0.0f;
#pragma unroll
        for (int e = 0; e < EE; e++) s += expf(acc[e] - mx);
        float w1 = expf(v1 - mx) / s;
        float w2 = expf(v2 - mx) / s;
        g_topk_idx[warp * 2 + 0] = i1;
        g_topk_idx[warp * 2 + 1] = i2;
        g_topk_w[warp * 2 + 0] = w1;
        g_topk_w[warp * 2 + 1] = w2;
    }
}

// ---------------- kernel 2: ordered rank scan + compaction ----------------
__global__ void scan_kernel() {
    __shared__ int cnt[512][EE];
    __shared__ int ecount[EE];
    int tid = threadIdx.x;
    int k = tid >> 8;
    int c = tid & 255;
    int t0 = c * 16;

#pragma unroll
    for (int e = 0; e < EE; e++) cnt[tid][e] = 0;
    if (tid < EE) ecount[tid] = 0;
    __syncthreads();

    for (int i = 0; i < 16; i++) {
        int e = g_topk_idx[(t0 + i) * 2 + k];
        cnt[tid][e]++;
    }
    __syncthreads();

    if (tid < 32) {
        int kk = tid >> 4, ee = tid & 15;
        int run = 0;
        for (int cc = 0; cc < 256; cc++) {
            int idx = kk * 256 + cc;
            int v = cnt[idx][ee];
            cnt[idx][ee] = run;
            run += v;
        }
    }
    __syncthreads();

    for (int i = 0; i < 16; i++) {
        int t = t0 + i;
        int e = g_topk_idx[t * 2 + k];
        float w = g_topk_w[t * 2 + k];
        int rank = cnt[tid][e]++;
        if (rank < CAP) {
            int slot = atomicAdd(&ecount[e], 1);
            g_disp_tok[e * CBUF + slot] = t;
            g_disp_w[e * CBUF + slot] = w;
        }
    }
    __syncthreads();
    if (tid < EE) g_count[tid] = ecount[tid];
}

// ---------------- kernel 3: gemm1 (ldmatrix + mma, reg-prefetch pipeline) -
__global__ __launch_bounds__(256, 1)
void gemm1_kernel() {
    int e    = blockIdx.z;
    int mcnt = g_count[e];
    mcnt = (mcnt < 0) ? 0 : ((mcnt > CBUF) ? CBUF : mcnt);
    int m0   = blockIdx.y * BM;
    if (m0 >= mcnt) return;
    int h0 = blockIdx.x * 64;

    __shared__ __align__(16) unsigned char sm[40960];
    __shared__ int s_tok[BM];

    int tid  = threadIdx.x;
    int lane = tid & 31;
    int w    = tid >> 5;
    int mat  = w >> 2;        // 0 = gate, 1 = up
    int wm   = (w >> 1) & 1;  // m half (64 rows)
    int wn   = w & 1;         // n half (32 cols)

    if (tid < BM) {
        int gr = m0 + tid;
        int tk = (gr < mcnt) ? g_disp_tok[e * CBUF + gr] : -1;
        if (tk < 0 || tk >= TT) tk = (gr < mcnt) ? 0 : -1;
        s_tok[tid] = tk;
    }
    __syncthreads();
    uint32_t sbase = smem_u32(sm);

    int rowA0 = tid >> 2;              // rows 0..63
    int rowA1 = rowA0 + 64;            // rows 64..127
    int c8 = tid & 3;
    int tokA0 = s_tok[rowA0];
    int tokA1 = s_tok[rowA1];
    int rowB = tid >> 2;               // 0..63

    float acc[4][4][4];
#pragma unroll
    for (int im = 0; im < 4; im++)
#pragma unroll
        for (int in = 0; in < 4; in++)
#pragma unroll
            for (int r = 0; r < 4; r++) acc[im][in][r] = 0.0f;

    const uint4 zero4 = {0, 0, 0, 0};
    int g = lane >> 2, q = lane & 3;

    uint32_t aHb = sbase + S1_AH;
    uint32_t aLb = sbase + S1_AL;
    uint32_t bHb = sbase + S1_B + mat * 10240;
    uint32_t bLb = bHb + 5120;
    int ar  = wm * 64 + (lane & 15);
    int akb = (lane >> 4) << 4;
    int br  = wn * 32 + (lane & 7);
    int bkb = ((lane >> 3) & 1) << 4;

    // register prefetch buffers
    uint4 pAh0, pAl0, pAh1, pAl1, pBgh, pBgl, pBuh, pBul;
    {
        size_t a0 = (size_t)(tokA0 < 0 ? 0 : tokA0) * DD + c8 * 8;
        size_t a1 = (size_t)(tokA1 < 0 ? 0 : tokA1) * DD + c8 * 8;
        pAh0 = (tokA0 >= 0) ? *(const uint4*)(g_xhi + a0) : zero4;
        pAl0 = (tokA0 >= 0) ? *(const uint4*)(g_xlo + a0) : zero4;
        pAh1 = (tokA1 >= 0) ? *(const uint4*)(g_xhi + a1) : zero4;
        pAl1 = (tokA1 >= 0) ? *(const uint4*)(g_xlo + a1) : zero4;
        size_t bb = ((size_t)e * HH + h0 + rowB) * DD + c8 * 8;
        pBgh = *(const uint4*)(g_gwThi + bb);
        pBgl = *(const uint4*)(g_gwTlo + bb);
        pBuh = *(const uint4*)(g_uwThi + bb);
        pBul = *(const uint4*)(g_uwTlo + bb);
    }

    for (int ch = 0; ch < NCH; ch++) {
        __syncthreads();   // previous compute done; smem free
        *(uint4*)(sm + S1_AH + rowA0 * ROWB + c8 * 16) = pAh0;
        *(uint4*)(sm + S1_AL + rowA0 * ROWB + c8 * 16) = pAl0;
        *(uint4*)(sm + S1_AH + rowA1 * ROWB + c8 * 16) = pAh1;
        *(uint4*)(sm + S1_AL + rowA1 * ROWB + c8 * 16) = pAl1;
        *(uint4*)(sm + S1_B + 0     + rowB * ROWB + c8 * 16) = pBgh;
        *(uint4*)(sm + S1_B + 5120  + rowB * ROWB + c8 * 16) = pBgl;
        *(uint4*)(sm + S1_B + 10240 + rowB * ROWB + c8 * 16) = pBuh;
        *(uint4*)(sm + S1_B + 15360 + rowB * ROWB + c8 * 16) = pBul;
        __syncthreads();

        if (ch + 1 < NCH) {   // prefetch next chunk; overlaps compute below
            int k0 = (ch + 1) * BK;
            size_t a0 = (size_t)(tokA0 < 0 ? 0 : tokA0) * DD + k0 + c8 * 8;
            size_t a1 = (size_t)(tokA1 < 0 ? 0 : tokA1) * DD + k0 + c8 * 8;
            pAh0 = (tokA0 >= 0) ? *(const uint4*)(g_xhi + a0) : zero4;
            pAl0 = (tokA0 >= 0) ? *(const uint4*)(g_xlo + a0) : zero4;
            pAh1 = (tokA1 >= 0) ? *(const uint4*)(g_xhi + a1) : zero4;
            pAl1 = (tokA1 >= 0) ? *(const uint4*)(g_xlo + a1) : zero4;
            size_t bb = ((size_t)e * HH + h0 + rowB) * DD + k0 + c8 * 8;
            pBgh = *(const uint4*)(g_gwThi + bb);
            pBgl = *(const uint4*)(g_gwTlo + bb);
            pBuh = *(const uint4*)(g_uwThi + bb);
            pBul = *(const uint4*)(g_uwTlo + bb);
        }

#pragma unroll
        for (int ks = 0; ks < 2; ks++) {
            uint32_t Bh[4][2], Bl[4][2];
#pragma unroll
            for (int in = 0; in < 4; in++) {
                uint32_t off = (uint32_t)(br + in * 8) * ROWB + ks * 32 + bkb;
                ldmx2(Bh[in], bHb + off);
                ldmx2(Bl[in], bLb + off);
            }
#pragma unroll
            for (int im = 0; im < 4; im++) {
                uint32_t Ah[4], Al[4];
                uint32_t off = (uint32_t)(ar + im * 16) * ROWB + ks * 32 + akb;
                ldmx4(Ah, aHb + off);
                ldmx4(Al, aLb + off);
                // pass-grouped: 4 independent accs between same-acc reuse
#pragma unroll
                for (int in = 0; in < 4; in++) mma_bf16(acc[im][in], Ah, Bh[in]);
#pragma unroll
                for (int in = 0; in < 4; in++) mma_bf16(acc[im][in], Ah, Bl[in]);
#pragma unroll
                for (int in = 0; in < 4; in++) mma_bf16(acc[im][in], Al, Bh[in]);
            }
        }
    }
    __syncthreads();

    // ---- epilogue: up warps stage to smem; gate warps fuse silu(g)*u ----
    float* ex = (float*)sm;   // 128 x 64 fp32 = 32 KB
    if (mat == 1) {
#pragma unroll
        for (int im = 0; im < 4; im++)
#pragma unroll
            for (int in = 0; in < 4; in++) {
                int rb = wm * 64 + im * 16 + g;
                int nb = wn * 32 + in * 8 + q * 2;
                ex[rb * 64 + nb]           = acc[im][in][0];
                ex[rb * 64 + nb + 1]       = acc[im][in][1];
                ex[(rb + 8) * 64 + nb]     = acc[im][in][2];
                ex[(rb + 8) * 64 + nb + 1] = acc[im][in][3];
            }
    }
    __syncthreads();
    if (mat == 0) {
#pragma unroll
        for (int im = 0; im < 4; im++)
#pragma unroll
            for (int in = 0; in < 4; in++) {
                int rb = wm * 64 + im * 16 + g;
                int nb = wn * 32 + in * 8 + q * 2;
#pragma unroll
                for (int h = 0; h < 2; h++) {
                    int r = rb + h * 8;
                    int gr = m0 + r;
                    if (gr < mcnt) {
                        float g0 = acc[im][in][h * 2], g1 = acc[im][in][h * 2 + 1];
                        float u0 = ex[r * 64 + nb], u1 = ex[r * 64 + nb + 1];
                        float f0 = (g0 / (1.0f + expf(-g0))) * u0;
                        float f1 = (g1 / (1.0f + expf(-g1))) * u1;
                        __nv_bfloat16 h0b = __float2bfloat16_rn(f0);
                        __nv_bfloat16 h1b = __float2bfloat16_rn(f1);
                        __nv_bfloat16 l0b = __float2bfloat16_rn(f0 - __bfloat162float(h0b));
                        __nv_bfloat16 l1b = __float2bfloat16_rn(f1 - __bfloat162float(h1b));
                        size_t o = ((size_t)e * CBUF + gr) * HH + h0 + nb;
                        __nv_bfloat162 vh; vh.x = h0b; vh.y = h1b;
                        __nv_bfloat162 vl; vl.x = l0b; vl.y = l1b;
                        *(__nv_bfloat162*)(g_hidhi + o) = vh;
                        *(__nv_bfloat162*)(g_hidlo + o) = vl;
                    }
                }
            }
    }
}

// ---------------- kernel 4: gemm2 (ldmatrix + mma, reg-prefetch) ----------
__global__ __launch_bounds__(256, 2)
void gemm2_kernel(float* __restrict__ out) {
    int e    = blockIdx.z;
    int mcnt = g_count[e];
    mcnt = (mcnt < 0) ? 0 : ((mcnt > CBUF) ? CBUF : mcnt);
    int m0   = blockIdx.y * BM;
    if (m0 >= mcnt) return;
    int d0 = blockIdx.x * 64;

    __shared__ __align__(16) unsigned char sm[30720];
    __shared__ int   s_tok[BM];
    __shared__ float s_w[BM];

    int tid  = threadIdx.x;
    int lane = tid & 31;
    int w    = tid >> 5;
    int wm   = w >> 1;   // 0..3
    int wn   = w & 1;    // 0..1

    if (tid < BM) {
        int gr = m0 + tid;
        bool v = gr < mcnt;
        int tk = v ? g_disp_tok[e * CBUF + gr] : 0;
        if (tk < 0 || tk >= TT) tk = 0;
        s_tok[tid] = tk;
        s_w[tid]   = v ? g_disp_w[e * CBUF + gr] : 0.0f;
    }
    __syncthreads();
    uint32_t sbase = smem_u32(sm);

    int rowA0 = tid >> 2;
    int rowA1 = rowA0 + 64;
    int c8 = tid & 3;
    bool vA0 = (m0 + rowA0) < mcnt;
    bool vA1 = (m0 + rowA1) < mcnt;
    int rowB = tid >> 2;

    float acc[2][4][4];
#pragma unroll
    for (int im = 0; im < 2; im++)
#pragma unroll
        for (int in = 0; in < 4; in++)
#pragma unroll
            for (int r = 0; r < 4; r++) acc[im][in][r] = 0.0f;

    const uint4 zero4 = {0, 0, 0, 0};
    int g = lane >> 2, q = lane & 3;

    uint32_t aHb = sbase + S2_AH;
    uint32_t aLb = sbase + S2_AL;
    uint32_t bHb = sbase + S2_BH;
    uint32_t bLb = sbase + S2_BL;
    int ar  = wm * 32 + (lane & 15);
    int akb = (lane >> 4) << 4;
    int br  = wn * 32 + (lane & 7);
    int bkb = ((lane >> 3) & 1) << 4;

    uint4 pAh0, pAl0, pAh1, pAl1, pBh, pBl;
    {
        size_t a0 = ((size_t)e * CBUF + (vA0 ? m0 + rowA0 : 0)) * HH + c8 * 8;
        size_t a1 = ((size_t)e * CBUF + (vA1 ? m0 + rowA1 : 0)) * HH + c8 * 8;
        pAh0 = vA0 ? *(const uint4*)(g_hidhi + a0) : zero4;
        pAl0 = vA0 ? *(const uint4*)(g_hidlo + a0) : zero4;
        pAh1 = vA1 ? *(const uint4*)(g_hidhi + a1) : zero4;
        pAl1 = vA1 ? *(const uint4*)(g_hidlo + a1) : zero4;
        size_t bb = ((size_t)e * DD + d0 + rowB) * HH + c8 * 8;
        pBh = *(const uint4*)(g_dwThi + bb);
        pBl = *(const uint4*)(g_dwTlo + bb);
    }

    for (int ch = 0; ch < NCH; ch++) {
        __syncthreads();
        *(uint4*)(sm + S2_AH + rowA0 * ROWB + c8 * 16) = pAh0;
        *(uint4*)(sm + S2_AL + rowA0 * ROWB + c8 * 16) = pAl0;
        *(uint4*)(sm + S2_AH + rowA1 * ROWB + c8 * 16) = pAh1;
        *(uint4*)(sm + S2_AL + rowA1 * ROWB + c8 * 16) = pAl1;
        *(uint4*)(sm + S2_BH + rowB * ROWB + c8 * 16) = pBh;
        *(uint4*)(sm + S2_BL + rowB * ROWB + c8 * 16) = pBl;
        __syncthreads();

        if (ch + 1 < NCH) {
            int k0 = (ch + 1) * BK;
            size_t a0 = ((size_t)e * CBUF + (vA0 ? m0 + rowA0 : 0)) * HH + k0 + c8 * 8;
            size_t a1 = ((size_t)e * CBUF + (vA1 ? m0 + rowA1 : 0)) * HH + k0 + c8 * 8;
            pAh0 = vA0 ? *(const uint4*)(g_hidhi + a0) : zero4;
            pAl0 = vA0 ? *(const uint4*)(g_hidlo + a0) : zero4;
            pAh1 = vA1 ? *(const uint4*)(g_hidhi + a1) : zero4;
            pAl1 = vA1 ? *(const uint4*)(g_hidlo + a1) : zero4;
            size_t bb = ((size_t)e * DD + d0 + rowB) * HH + k0 + c8 * 8;
            pBh = *(const uint4*)(g_dwThi + bb);
            pBl = *(const uint4*)(g_dwTlo + bb);
        }

#pragma unroll
        for (int ks = 0; ks < 2; ks++) {
            uint32_t Bh[4][2], Bl[4][2];
#pragma unroll
            for (int in = 0; in < 4; in++) {
                uint32_t off = (uint32_t)(br + in * 8) * ROWB + ks * 32 + bkb;
                ldmx2(Bh[in], bHb + off);
                ldmx2(Bl[in], bLb + off);
            }
#pragma unroll
            for (int im = 0; im < 2; im++) {
                uint32_t Ah[4], Al[4];
                uint32_t off = (uint32_t)(ar + im * 16) * ROWB + ks * 32 + akb;
                ldmx4(Ah, aHb + off);
                ldmx4(Al, aLb + off);
#pragma unroll
                for (int in = 0; in < 4; in++) mma_bf16(acc[im][in], Ah, Bh[in]);
#pragma unroll
                for (int in = 0; in < 4; in++) mma_bf16(acc[im][in], Ah, Bl[in]);
#pragma unroll
                for (int in = 0; in < 4; in++) mma_bf16(acc[im][in], Al, Bh[in]);
            }
        }
    }

    // epilogue: weighted scatter-add into output
#pragma unroll
    for (int im = 0; im < 2; im++)
#pragma unroll
        for (int in = 0; in < 4; in++) {
            int rb = wm * 32 + im * 16 + g;
            int nb = wn * 32 + in * 8 + q * 2;
#pragma unroll
            for (int h = 0; h < 2; h++) {
                int r = rb + h * 8;
                int gr = m0 + r;
                if (gr < mcnt) {
                    float wt = s_w[r];
                    float* op = out + (size_t)s_tok[r] * DD + d0 + nb;
                    atomicAdd(op + 0, acc[im][in][h * 2] * wt);
                    atomicAdd(op + 1, acc[im][in][h * 2 + 1] * wt);
                }
            }
        }
}

// ---------------- launcher ----------------
// Launch order puts gemm1 at launch index 3 (the ncu capture point).
extern "C" void kernel_launch(void* const* d_in, const int* in_sizes, int n_in,
                              void* d_out, int out_size) {
    const float* x  = (const float*)d_in[0];
    const float* rw = (const float*)d_in[1];
    const float* gw = (const float*)d_in[2];
    const float* uw = (const float*)d_in[3];
    const float* dw = (const float*)d_in[4];
    float* out = (float*)d_out;

    prep_kernel<<<dim3(32, 32, 49), dim3(32, 8)>>>(x, gw, uw, dw);   // idx 0
    router_kernel<<<TT / 8, 256>>>(x, rw, out);                      // idx 1
    scan_kernel<<<1, 512>>>();                                       // idx 2
    gemm1_kernel<<<dim3(HH / 64, CBUF / BM, EE), 256>>>();           // idx 3
    gemm2_kernel<<<dim3(DD / 64, CBUF / BM, EE), 256>>>(out);        // idx 4
}